// round 1
// baseline (speedup 1.0000x reference)
#include <cuda_runtime.h>
#include <cuda_bf16.h>
#include <cstdint>

// Problem constants
#define BATCH 4
#define SLEN  4096
#define HID   1024
#define MTOT  (BATCH * SLEN)   // 16384

// ---------------- scratch (device globals: no runtime allocation) ----------------
__device__ float g_q[(size_t)MTOT * HID];
__device__ float g_k[(size_t)MTOT * HID];
__device__ float g_v[(size_t)MTOT * HID];

// =================================================================================
// Kernel 1: C[m,n] = sum_k X[m,k] * W[n,k]   (X: [M,1024], W: [1024,1024] row-major)
// 128x128 tile, BK=8, 256 threads, 8x8 microtile, register prefetch.
// =================================================================================
__global__ void __launch_bounds__(256, 2) gemm_xwT(const float* __restrict__ X,
                                                   const float* __restrict__ W,
                                                   float* __restrict__ C) {
    __shared__ float As[8][128];
    __shared__ float Bs[8][128];

    const int tid = threadIdx.x;
    const int m0 = blockIdx.y * 128;
    const int n0 = blockIdx.x * 128;
    const int tx = tid & 15;
    const int ty = tid >> 4;

    const int arow = tid >> 1;        // 0..127
    const int acol = (tid & 1) * 4;   // 0 or 4

    const float* Ag = X + (size_t)(m0 + arow) * HID + acol;
    const float* Bg = W + (size_t)(n0 + arow) * HID + acol;

    float acc[8][8];
#pragma unroll
    for (int i = 0; i < 8; i++)
#pragma unroll
        for (int j = 0; j < 8; j++) acc[i][j] = 0.0f;

    float4 apre = *(const float4*)(Ag);
    float4 bpre = *(const float4*)(Bg);

    for (int kt = 0; kt < HID; kt += 8) {
        As[acol + 0][arow] = apre.x;
        As[acol + 1][arow] = apre.y;
        As[acol + 2][arow] = apre.z;
        As[acol + 3][arow] = apre.w;
        Bs[acol + 0][arow] = bpre.x;
        Bs[acol + 1][arow] = bpre.y;
        Bs[acol + 2][arow] = bpre.z;
        Bs[acol + 3][arow] = bpre.w;
        __syncthreads();

        if (kt + 8 < HID) {
            apre = *(const float4*)(Ag + kt + 8);
            bpre = *(const float4*)(Bg + kt + 8);
        }

#pragma unroll
        for (int k = 0; k < 8; k++) {
            float4 a0 = *(const float4*)(&As[k][ty * 8]);
            float4 a1 = *(const float4*)(&As[k][ty * 8 + 4]);
            float4 b0 = *(const float4*)(&Bs[k][tx * 8]);
            float4 b1 = *(const float4*)(&Bs[k][tx * 8 + 4]);
            float ra[8] = {a0.x, a0.y, a0.z, a0.w, a1.x, a1.y, a1.z, a1.w};
            float rb[8] = {b0.x, b0.y, b0.z, b0.w, b1.x, b1.y, b1.z, b1.w};
#pragma unroll
            for (int i = 0; i < 8; i++)
#pragma unroll
                for (int j = 0; j < 8; j++) acc[i][j] += ra[i] * rb[j];
        }
        __syncthreads();
    }

#pragma unroll
    for (int i = 0; i < 8; i++) {
        float4 c0 = make_float4(acc[i][0], acc[i][1], acc[i][2], acc[i][3]);
        float4 c1 = make_float4(acc[i][4], acc[i][5], acc[i][6], acc[i][7]);
        float* crow = C + (size_t)(m0 + ty * 8 + i) * HID + n0 + tx * 8;
        *(float4*)(crow) = c0;
        *(float4*)(crow + 4) = c1;
    }
}

// =================================================================================
// Kernel 2: causal flash attention, fp32, one CTA per (batch, 16-query tile).
// SMEM: Q tile [16][1028], O acc [16][1028], K/V chunk [128][132], P [16][132].
// =================================================================================
#define BQ    16
#define BKEY  128
#define HC    128
#define QSTR  1028
#define KSTR  132
#define PSTR  132

#define SM_QS 0
#define SM_OS (SM_QS + BQ * QSTR)                // 16448
#define SM_KV (SM_OS + BQ * QSTR)                // 32896
#define SM_PS (SM_KV + BKEY * KSTR)              // 49792
#define SM_M  (SM_PS + BQ * PSTR)                // 51904
#define SM_L  (SM_M + BQ)
#define SM_A  (SM_L + BQ)
#define SM_FLOATS (SM_A + BQ)                    // 51952
#define ATTN_SMEM_BYTES (SM_FLOATS * 4)          // 207808 B

__global__ void __launch_bounds__(256, 1) attn_kernel(float* __restrict__ out) {
    extern __shared__ float sm[];
    float* Qs   = sm + SM_QS;
    float* Os   = sm + SM_OS;
    float* KVs  = sm + SM_KV;
    float* Ps   = sm + SM_PS;
    float* mrow = sm + SM_M;
    float* lrow = sm + SM_L;
    float* arow = sm + SM_A;

    const int tid = threadIdx.x;
    const int b   = blockIdx.y;
    const int qt  = blockIdx.x;
    const int q0  = qt * BQ;

    const float* Qg = g_q + ((size_t)b * SLEN + q0) * HID;
    const float* Kg = g_k + (size_t)b * SLEN * HID;
    const float* Vg = g_v + (size_t)b * SLEN * HID;

    // load Q tile, zero O accumulator
    for (int i = tid; i < BQ * HID / 4; i += 256) {
        int q  = i >> 8;       // HID/4 = 256
        int h4 = i & 255;
        float4 v = *(const float4*)(Qg + (size_t)q * HID + h4 * 4);
        *(float4*)(Qs + q * QSTR + h4 * 4) = v;
        float4 z = make_float4(0.f, 0.f, 0.f, 0.f);
        *(float4*)(Os + q * QSTR + h4 * 4) = z;
    }
    if (tid < BQ) { mrow[tid] = -3.0e38f; lrow[tid] = 0.0f; }
    __syncthreads();

    const float scale = 0.03125f;  // 1/sqrt(1024)
    const int q_end = q0 + BQ - 1;
    const int nkb = q_end / BKEY + 1;

    const int tk = tid & 31;   // score: keys 4tk..4tk+3
    const int tq = tid >> 5;   // score: queries 2tq, 2tq+1
    const int hg = tid & 31;   // PV: h group (4 floats)
    const int qp = tid >> 5;   // PV: query pair

    for (int kb = 0; kb < nkb; kb++) {
        const int k0 = kb * BKEY;

        float acc0[4] = {0.f, 0.f, 0.f, 0.f};
        float acc1[4] = {0.f, 0.f, 0.f, 0.f};

        // ---- S = Q K^T over h chunks ----
        for (int hc = 0; hc < HID; hc += HC) {
            for (int i = tid; i < BKEY * HC / 4; i += 256) {
                int k  = i >> 5;   // HC/4 = 32
                int h4 = i & 31;
                float4 v = *(const float4*)(Kg + (size_t)(k0 + k) * HID + hc + h4 * 4);
                *(float4*)(KVs + k * KSTR + h4 * 4) = v;
            }
            __syncthreads();

            const float* qr0 = Qs + (2 * tq) * QSTR + hc;
            const float* qr1 = qr0 + QSTR;
#pragma unroll 8
            for (int h4 = 0; h4 < HC / 4; h4++) {
                float4 qa = *(const float4*)(qr0 + h4 * 4);
                float4 qb = *(const float4*)(qr1 + h4 * 4);
#pragma unroll
                for (int j = 0; j < 4; j++) {
                    float4 kv = *(const float4*)(KVs + (4 * tk + j) * KSTR + h4 * 4);
                    acc0[j] += qa.x * kv.x + qa.y * kv.y + qa.z * kv.z + qa.w * kv.w;
                    acc1[j] += qb.x * kv.x + qb.y * kv.y + qb.z * kv.z + qb.w * kv.w;
                }
            }
            __syncthreads();
        }

        // ---- masked scores into Ps ----
#pragma unroll
        for (int j = 0; j < 4; j++) {
            int kg = k0 + 4 * tk + j;
            int qg0 = q0 + 2 * tq;
            Ps[(2 * tq) * PSTR + 4 * tk + j]     = (kg <= qg0)     ? acc0[j] * scale : -3.0e38f;
            Ps[(2 * tq + 1) * PSTR + 4 * tk + j] = (kg <= qg0 + 1) ? acc1[j] * scale : -3.0e38f;
        }
        __syncthreads();

        // ---- online softmax (16 lanes per row) ----
        {
            const int r = tid >> 4;
            const int c = tid & 15;
            float mx = -3.0e38f;
#pragma unroll
            for (int i = 0; i < 8; i++) mx = fmaxf(mx, Ps[r * PSTR + c * 8 + i]);
#pragma unroll
            for (int o = 8; o; o >>= 1) mx = fmaxf(mx, __shfl_xor_sync(0xffffffffu, mx, o, 16));
            float mnew = fmaxf(mrow[r], mx);
            float sum = 0.f;
#pragma unroll
            for (int i = 0; i < 8; i++) {
                float p = __expf(Ps[r * PSTR + c * 8 + i] - mnew);
                Ps[r * PSTR + c * 8 + i] = p;
                sum += p;
            }
#pragma unroll
            for (int o = 8; o; o >>= 1) sum += __shfl_xor_sync(0xffffffffu, sum, o, 16);
            if (c == 0) {
                float a = __expf(mrow[r] - mnew);
                arow[r] = a;
                lrow[r] = lrow[r] * a + sum;
                mrow[r] = mnew;
            }
        }
        __syncthreads();

        // ---- rescale O ----
        for (int i = tid; i < BQ * HID / 4; i += 256) {
            int q  = i >> 8;
            int h4 = i & 255;
            float a = arow[q];
            float4 o = *(float4*)(Os + q * QSTR + h4 * 4);
            o.x *= a; o.y *= a; o.z *= a; o.w *= a;
            *(float4*)(Os + q * QSTR + h4 * 4) = o;
        }
        __syncthreads();

        // ---- O += P V over h chunks ----
        for (int hc = 0; hc < HID; hc += HC) {
            for (int i = tid; i < BKEY * HC / 4; i += 256) {
                int k  = i >> 5;
                int h4 = i & 31;
                float4 v = *(const float4*)(Vg + (size_t)(k0 + k) * HID + hc + h4 * 4);
                *(float4*)(KVs + k * KSTR + h4 * 4) = v;
            }
            __syncthreads();

            float4 o0 = *(float4*)(Os + (2 * qp) * QSTR + hc + 4 * hg);
            float4 o1 = *(float4*)(Os + (2 * qp + 1) * QSTR + hc + 4 * hg);
            const float* p0 = Ps + (2 * qp) * PSTR;
            const float* p1 = p0 + PSTR;
#pragma unroll 4
            for (int k = 0; k < BKEY; k++) {
                float4 v = *(const float4*)(KVs + k * KSTR + 4 * hg);
                float a0 = p0[k];
                float a1 = p1[k];
                o0.x += a0 * v.x; o0.y += a0 * v.y; o0.z += a0 * v.z; o0.w += a0 * v.w;
                o1.x += a1 * v.x; o1.y += a1 * v.y; o1.z += a1 * v.z; o1.w += a1 * v.w;
            }
            *(float4*)(Os + (2 * qp) * QSTR + hc + 4 * hg) = o0;
            *(float4*)(Os + (2 * qp + 1) * QSTR + hc + 4 * hg) = o1;
            __syncthreads();
        }
    }

    // ---- normalize and write out ----
    for (int i = tid; i < BQ * HID / 4; i += 256) {
        int q  = i >> 8;
        int h4 = i & 255;
        float inv = 1.0f / lrow[q];
        float4 o = *(float4*)(Os + q * QSTR + h4 * 4);
        o.x *= inv; o.y *= inv; o.z *= inv; o.w *= inv;
        *(float4*)(out + ((size_t)b * SLEN + q0 + q) * HID + h4 * 4) = o;
    }
}

// =================================================================================
// Launch
// =================================================================================
extern "C" void kernel_launch(void* const* d_in, const int* in_sizes, int n_in,
                              void* d_out, int out_size) {
    (void)in_sizes; (void)n_in; (void)out_size;
    const float* x  = (const float*)d_in[0];
    const float* Wq = (const float*)d_in[1];
    const float* Wk = (const float*)d_in[2];
    const float* Wv = (const float*)d_in[3];
    float* out = (float*)d_out;

    float* dq; cudaGetSymbolAddress((void**)&dq, g_q);
    float* dk; cudaGetSymbolAddress((void**)&dk, g_k);
    float* dv; cudaGetSymbolAddress((void**)&dv, g_v);

    dim3 ggrid(HID / 128, MTOT / 128);   // (8, 128)
    gemm_xwT<<<ggrid, 256>>>(x, Wq, dq);
    gemm_xwT<<<ggrid, 256>>>(x, Wk, dk);
    gemm_xwT<<<ggrid, 256>>>(x, Wv, dv);

    static bool attr_set = false;
    if (!attr_set) {
        cudaFuncSetAttribute(attn_kernel, cudaFuncAttributeMaxDynamicSharedMemorySize,
                             ATTN_SMEM_BYTES);
        attr_set = true;
    }
    dim3 agrid(SLEN / BQ, BATCH);        // (256, 4)
    attn_kernel<<<agrid, 256, ATTN_SMEM_BYTES>>>(out);
}

// round 2
// speedup vs baseline: 9.7279x; 9.7279x over previous
#include <cuda_runtime.h>
#include <cuda_bf16.h>
#include <cstdint>

// ---------------- problem constants ----------------
#define BATCH 4
#define SLEN  4096
#define HID   1024
#define MTOT  (BATCH * SLEN)     // 16384
#define KEXT  3072               // 3 * HID   (hi/lo extension over h)
#define KPV   12288              // 3 * SLEN  (hi/lo extension over keys)
#define ASTR  72                 // smem row stride (bf16 elems), 128B rows + 16B pad

// ---------------- static scratch (no runtime allocation) ----------------
__device__ __nv_bfloat16 g_xext [(size_t)MTOT * KEXT];        // [xhi|xhi|xlo]
__device__ __nv_bfloat16 g_wext [(size_t)HID  * KEXT];        // [whi|wlo|whi]
__device__ __nv_bfloat16 g_qext [(size_t)MTOT * KEXT];        // [qhi|qhi|qlo]
__device__ __nv_bfloat16 g_kext [(size_t)MTOT * KEXT];        // [khi|klo|khi]
__device__ __nv_bfloat16 g_vtext[(size_t)BATCH * HID * KPV];  // [b][h][vhi|vlo|vhi]
__device__ float         g_S    [(size_t)BATCH * SLEN * SLEN];// raw scores
__device__ __nv_bfloat16 g_pext [(size_t)MTOT * KPV];         // [phi|phi|plo], zero-padded

// ---------------- helpers ----------------
__device__ __forceinline__ uint32_t smem_u32(const void* p) {
    return (uint32_t)__cvta_generic_to_shared(p);
}

#define LDMX4(R0, R1, R2, R3, addr)                                            \
    asm volatile("ldmatrix.sync.aligned.m8n8.x4.shared.b16 {%0,%1,%2,%3}, [%4];" \
                 : "=r"(R0), "=r"(R1), "=r"(R2), "=r"(R3) : "r"(addr))

#define MMA16816(C, A0, A1, A2, A3, B0, B1)                                    \
    asm volatile("mma.sync.aligned.m16n8k16.row.col.f32.bf16.bf16.f32 "        \
                 "{%0,%1,%2,%3}, {%4,%5,%6,%7}, {%8,%9}, {%0,%1,%2,%3};"       \
                 : "+f"(C[0]), "+f"(C[1]), "+f"(C[2]), "+f"(C[3])              \
                 : "r"(A0), "r"(A1), "r"(A2), "r"(A3), "r"(B0), "r"(B1))

// =================================================================================
// Shared tile engine: acc += A[128 x 64*nChunks] * B[128 x 64*nChunks]^T
// Both operands K-major ([row][k]). 256 threads, 8 warps (4x2), warp tile 32x64.
// =================================================================================
__device__ __forceinline__ void gemm_accum(const __nv_bfloat16* __restrict__ Ag, long lda,
                                           const __nv_bfloat16* __restrict__ Bg, long ldb,
                                           int nChunks, float (&acc)[2][8][4],
                                           __nv_bfloat16* As, __nv_bfloat16* Bs) {
    const int tid  = threadIdx.x;
    const int r0   = tid >> 3;            // 0..31
    const int cg   = (tid & 7) * 8;       // 0..56
    const int wid  = tid >> 5;
    const int lane = tid & 31;
    const int wm   = (wid & 3) * 32;
    const int wn   = (wid >> 2) * 64;
    const int lrow = lane & 15;
    const int lk   = (lane >> 4) * 8;
    const uint32_t aSh = smem_u32(As);
    const uint32_t bSh = smem_u32(Bs);

    uint4 ra[4], rb[4];
#pragma unroll
    for (int i = 0; i < 4; i++) {
        ra[i] = *(const uint4*)(Ag + (size_t)(r0 + 32 * i) * lda + cg);
        rb[i] = *(const uint4*)(Bg + (size_t)(r0 + 32 * i) * ldb + cg);
    }

    for (int kc = 0; kc < nChunks; kc++) {
#pragma unroll
        for (int i = 0; i < 4; i++) {
            *(uint4*)(As + (r0 + 32 * i) * ASTR + cg) = ra[i];
            *(uint4*)(Bs + (r0 + 32 * i) * ASTR + cg) = rb[i];
        }
        __syncthreads();

        if (kc + 1 < nChunks) {
            const __nv_bfloat16* An = Ag + (size_t)(kc + 1) * 64;
            const __nv_bfloat16* Bn = Bg + (size_t)(kc + 1) * 64;
#pragma unroll
            for (int i = 0; i < 4; i++) {
                ra[i] = *(const uint4*)(An + (size_t)(r0 + 32 * i) * lda + cg);
                rb[i] = *(const uint4*)(Bn + (size_t)(r0 + 32 * i) * ldb + cg);
            }
        }

#pragma unroll
        for (int ks = 0; ks < 4; ks++) {
            uint32_t a[2][4];
#pragma unroll
            for (int mt = 0; mt < 2; mt++) {
                uint32_t addr = aSh + ((wm + mt * 16 + lrow) * ASTR + ks * 16 + lk) * 2;
                LDMX4(a[mt][0], a[mt][1], a[mt][2], a[mt][3], addr);
            }
#pragma unroll
            for (int g = 0; g < 4; g++) {
                uint32_t b0, b1, b2, b3;
                uint32_t addr = bSh + ((wn + g * 16 + lrow) * ASTR + ks * 16 + lk) * 2;
                LDMX4(b0, b1, b2, b3, addr);
#pragma unroll
                for (int mt = 0; mt < 2; mt++) {
                    MMA16816(acc[mt][2 * g],     a[mt][0], a[mt][1], a[mt][2], a[mt][3], b0, b2);
                    MMA16816(acc[mt][2 * g + 1], a[mt][0], a[mt][1], a[mt][2], a[mt][3], b1, b3);
                }
            }
        }
        __syncthreads();
    }
}

// =================================================================================
// Projection GEMM: C = Xext @ Wext^T, epilogue writes hi/lo split directly.
// mode 0: q -> qext [qhi|qhi|qlo]; mode 1: k -> kext [khi|klo|khi];
// mode 2: v -> vtext[b][h][vhi|vlo|vhi] (transposed).
// =================================================================================
__global__ void __launch_bounds__(256) proj_gemm(int mode) {
    __shared__ __align__(16) __nv_bfloat16 As[128 * ASTR];
    __shared__ __align__(16) __nv_bfloat16 Bs[128 * ASTR];
    float acc[2][8][4];
#pragma unroll
    for (int a = 0; a < 2; a++)
#pragma unroll
        for (int b = 0; b < 8; b++)
#pragma unroll
            for (int c = 0; c < 4; c++) acc[a][b][c] = 0.0f;

    const int m0 = blockIdx.y * 128;
    const int n0 = blockIdx.x * 128;
    gemm_accum(g_xext + (size_t)m0 * KEXT, KEXT,
               g_wext + (size_t)n0 * KEXT, KEXT, KEXT / 64, acc, As, Bs);

    const int tid = threadIdx.x, wid = tid >> 5, lane = tid & 31;
    const int wm = (wid & 3) * 32, wn = (wid >> 2) * 64;
    const int g = lane >> 2, t2 = (lane & 3) * 2;
#pragma unroll
    for (int mt = 0; mt < 2; mt++)
#pragma unroll
        for (int nt = 0; nt < 8; nt++)
#pragma unroll
            for (int ci = 0; ci < 4; ci++) {
                int m = m0 + wm + mt * 16 + g + ((ci >> 1) << 3);
                int n = n0 + wn + nt * 8 + t2 + (ci & 1);
                float c = acc[mt][nt][ci];
                __nv_bfloat16 hi = __float2bfloat16(c);
                __nv_bfloat16 lo = __float2bfloat16(c - __bfloat162float(hi));
                if (mode == 0) {
                    size_t base = (size_t)m * KEXT + n;
                    g_qext[base] = hi; g_qext[base + 1024] = hi; g_qext[base + 2048] = lo;
                } else if (mode == 1) {
                    size_t base = (size_t)m * KEXT + n;
                    g_kext[base] = hi; g_kext[base + 1024] = lo; g_kext[base + 2048] = hi;
                } else {
                    int b = m >> 12, j = m & 4095;
                    size_t base = ((size_t)b * HID + n) * KPV + j;
                    g_vtext[base] = hi; g_vtext[base + 4096] = lo; g_vtext[base + 8192] = hi;
                }
            }
}

// =================================================================================
// Score GEMM: S[b][q][k] = qext . kext (raw, unscaled). Skips fully-masked tiles.
// =================================================================================
__global__ void __launch_bounds__(256) scores_gemm() {
    const int m0 = blockIdx.y * 128;   // query tile
    const int n0 = blockIdx.x * 128;   // key tile
    if (n0 > m0 + 127) return;         // fully above diagonal
    const int b = blockIdx.z;

    __shared__ __align__(16) __nv_bfloat16 As[128 * ASTR];
    __shared__ __align__(16) __nv_bfloat16 Bs[128 * ASTR];
    float acc[2][8][4];
#pragma unroll
    for (int a = 0; a < 2; a++)
#pragma unroll
        for (int x = 0; x < 8; x++)
#pragma unroll
            for (int c = 0; c < 4; c++) acc[a][x][c] = 0.0f;

    gemm_accum(g_qext + (size_t)(b * SLEN + m0) * KEXT, KEXT,
               g_kext + (size_t)(b * SLEN + n0) * KEXT, KEXT, KEXT / 64, acc, As, Bs);

    const int tid = threadIdx.x, wid = tid >> 5, lane = tid & 31;
    const int wm = (wid & 3) * 32, wn = (wid >> 2) * 64;
    const int g = lane >> 2, t2 = (lane & 3) * 2;
#pragma unroll
    for (int mt = 0; mt < 2; mt++)
#pragma unroll
        for (int nt = 0; nt < 8; nt++)
#pragma unroll
            for (int ci = 0; ci < 4; ci++) {
                int m = m0 + wm + mt * 16 + g + ((ci >> 1) << 3);
                int n = n0 + wn + nt * 8 + t2 + (ci & 1);
                g_S[((size_t)b * SLEN + m) * SLEN + n] = acc[mt][nt][ci];
            }
}

// =================================================================================
// Row softmax: S -> Pext (bf16 hi/lo), normalized, zero-padded to 128-row tile end.
// One block per row.
// =================================================================================
__global__ void __launch_bounds__(256) softmax_kernel() {
    __shared__ float buf[SLEN];
    __shared__ float red[16];

    const int row = blockIdx.x;             // global row b*4096 + i
    const int i   = row & (SLEN - 1);
    const int tid = threadIdx.x, wid = tid >> 5, lane = tid & 31;
    const float scale = 0.03125f;           // 1/sqrt(1024)
    const float* srow = g_S + (size_t)row * SLEN;
    const int n    = i + 1;                 // valid keys
    const int jpad = ((i >> 7) + 1) << 7;   // zero-pad bound (tile end)

    float lm = -3.0e38f;
    for (int j = tid; j < n; j += 256) lm = fmaxf(lm, srow[j]);
#pragma unroll
    for (int o = 16; o; o >>= 1) lm = fmaxf(lm, __shfl_xor_sync(0xffffffffu, lm, o));
    if (lane == 0) red[wid] = lm;
    __syncthreads();
    if (tid == 0) {
        float m = red[0];
#pragma unroll
        for (int w = 1; w < 8; w++) m = fmaxf(m, red[w]);
        red[0] = m;
    }
    __syncthreads();
    const float mx = red[0];

    float ls = 0.0f;
    for (int j = tid; j < n; j += 256) {
        float e = __expf((srow[j] - mx) * scale);
        buf[j] = e;
        ls += e;
    }
#pragma unroll
    for (int o = 16; o; o >>= 1) ls += __shfl_xor_sync(0xffffffffu, ls, o);
    if (lane == 0) red[8 + wid] = ls;
    __syncthreads();
    if (tid == 0) {
        float s = 0.0f;
#pragma unroll
        for (int w = 0; w < 8; w++) s += red[8 + w];
        red[8] = 1.0f / s;
    }
    __syncthreads();
    const float inv = red[8];

    __nv_bfloat16* prow = g_pext + (size_t)row * KPV;
    for (int j = tid; j < jpad; j += 256) {
        float p = (j < n) ? buf[j] * inv : 0.0f;
        __nv_bfloat16 hi = __float2bfloat16(p);
        __nv_bfloat16 lo = __float2bfloat16(p - __bfloat162float(hi));
        prow[j] = hi;
        prow[SLEN + j] = hi;
        prow[2 * SLEN + j] = lo;
    }
}

// =================================================================================
// PV GEMM: out[b][q][h] = Pext . Vtext over 3 segments, K truncated per query tile.
// =================================================================================
__global__ void __launch_bounds__(256) pv_gemm(float* __restrict__ out) {
    __shared__ __align__(16) __nv_bfloat16 As[128 * ASTR];
    __shared__ __align__(16) __nv_bfloat16 Bs[128 * ASTR];
    float acc[2][8][4];
#pragma unroll
    for (int a = 0; a < 2; a++)
#pragma unroll
        for (int x = 0; x < 8; x++)
#pragma unroll
            for (int c = 0; c < 4; c++) acc[a][x][c] = 0.0f;

    const int m0 = blockIdx.y * 128;   // query tile
    const int n0 = blockIdx.x * 128;   // h tile
    const int b  = blockIdx.z;
    const int nc = (m0 + 128) >> 6;    // live chunks per segment

    const __nv_bfloat16* A = g_pext  + (size_t)(b * SLEN + m0) * KPV;
    const __nv_bfloat16* B = g_vtext + ((size_t)b * HID + n0) * KPV;
#pragma unroll
    for (int seg = 0; seg < 3; seg++)
        gemm_accum(A + seg * SLEN, KPV, B + seg * SLEN, KPV, nc, acc, As, Bs);

    const int tid = threadIdx.x, wid = tid >> 5, lane = tid & 31;
    const int wm = (wid & 3) * 32, wn = (wid >> 2) * 64;
    const int g = lane >> 2, t2 = (lane & 3) * 2;
#pragma unroll
    for (int mt = 0; mt < 2; mt++)
#pragma unroll
        for (int nt = 0; nt < 8; nt++)
#pragma unroll
            for (int ci = 0; ci < 4; ci++) {
                int m = m0 + wm + mt * 16 + g + ((ci >> 1) << 3);
                int n = n0 + wn + nt * 8 + t2 + (ci & 1);
                out[((size_t)b * SLEN + m) * HID + n] = acc[mt][nt][ci];
            }
}

// =================================================================================
// Split kernels
// =================================================================================
__global__ void __launch_bounds__(256) split_x(const float* __restrict__ x) {
    size_t idx = (size_t)blockIdx.x * 256 + threadIdx.x;   // over MTOT*HID
    int m = (int)(idx >> 10), h = (int)(idx & 1023);
    float v = x[idx];
    __nv_bfloat16 hi = __float2bfloat16(v);
    __nv_bfloat16 lo = __float2bfloat16(v - __bfloat162float(hi));
    size_t base = (size_t)m * KEXT + h;
    g_xext[base] = hi; g_xext[base + 1024] = hi; g_xext[base + 2048] = lo;
}

__global__ void __launch_bounds__(256) split_w(const float* __restrict__ W) {
    size_t idx = (size_t)blockIdx.x * 256 + threadIdx.x;   // over HID*HID
    int n = (int)(idx >> 10), h = (int)(idx & 1023);
    float v = W[idx];
    __nv_bfloat16 hi = __float2bfloat16(v);
    __nv_bfloat16 lo = __float2bfloat16(v - __bfloat162float(hi));
    size_t base = (size_t)n * KEXT + h;
    g_wext[base] = hi; g_wext[base + 1024] = lo; g_wext[base + 2048] = hi;
}

// =================================================================================
// Launch
// =================================================================================
extern "C" void kernel_launch(void* const* d_in, const int* in_sizes, int n_in,
                              void* d_out, int out_size) {
    (void)in_sizes; (void)n_in; (void)out_size;
    const float* x  = (const float*)d_in[0];
    const float* Wq = (const float*)d_in[1];
    const float* Wk = (const float*)d_in[2];
    const float* Wv = (const float*)d_in[3];
    float* out = (float*)d_out;

    split_x<<<(MTOT * HID) / 256, 256>>>(x);

    dim3 pgrid(HID / 128, MTOT / 128);                 // (8, 128)
    split_w<<<(HID * HID) / 256, 256>>>(Wq);
    proj_gemm<<<pgrid, 256>>>(0);
    split_w<<<(HID * HID) / 256, 256>>>(Wk);
    proj_gemm<<<pgrid, 256>>>(1);
    split_w<<<(HID * HID) / 256, 256>>>(Wv);
    proj_gemm<<<pgrid, 256>>>(2);

    scores_gemm<<<dim3(SLEN / 128, SLEN / 128, BATCH), 256>>>();
    softmax_kernel<<<MTOT, 256>>>();
    pv_gemm<<<dim3(HID / 128, SLEN / 128, BATCH), 256>>>(out);
}

// round 4
// speedup vs baseline: 10.3511x; 1.0641x over previous
#include <cuda_runtime.h>
#include <cuda_bf16.h>
#include <cstdint>

#define BATCH 4
#define SLEN  4096
#define HID   1024
#define MTOT  (BATCH * SLEN)   // 16384

// ---------------- static scratch (no runtime allocation) ----------------
__device__ __align__(16) __nv_bfloat16 g_xhi[(size_t)MTOT * HID];
__device__ __align__(16) __nv_bfloat16 g_xlo[(size_t)MTOT * HID];
__device__ __align__(16) __nv_bfloat16 g_whi[(size_t)HID * HID];
__device__ __align__(16) __nv_bfloat16 g_wlo[(size_t)HID * HID];
__device__ __align__(16) __nv_bfloat16 g_qhi[(size_t)MTOT * HID];
__device__ __align__(16) __nv_bfloat16 g_qlo[(size_t)MTOT * HID];
__device__ __align__(16) __nv_bfloat16 g_khi[(size_t)MTOT * HID];
__device__ __align__(16) __nv_bfloat16 g_klo[(size_t)MTOT * HID];
__device__ __align__(16) __nv_bfloat16 g_vhi[(size_t)MTOT * HID];
__device__ __align__(16) __nv_bfloat16 g_vlo[(size_t)MTOT * HID];
__device__ __align__(16) __nv_bfloat16 g_vthi[(size_t)MTOT * HID];   // [b][h][s]
__device__ __align__(16) __nv_bfloat16 g_vtlo[(size_t)MTOT * HID];
__device__ __align__(16) __nv_bfloat16 g_phi[(size_t)MTOT * SLEN];   // zero-padded
__device__ __align__(16) __nv_bfloat16 g_plo[(size_t)MTOT * SLEN];
__device__ __align__(16) float         g_S  [(size_t)BATCH * SLEN * SLEN];

// ---------------- engine constants ----------------
#define CHUNK_K   32
#define ASTR2     72                          // row stride in bf16 elems (64 data + 8 pad)
#define SMO_B     18432                       // 128*72*2
#define STAGE_BYTES 36864                     // A + B planes per stage
#define ENG_SMEM  (3 * STAGE_BYTES)           // 110592

__device__ __forceinline__ uint32_t smem_u32(const void* p) {
    return (uint32_t)__cvta_generic_to_shared(p);
}

#define CP_ASYNC16(dst, src) \
    asm volatile("cp.async.cg.shared.global [%0], [%1], 16;" :: "r"(dst), "l"(src) : "memory")

#define LDMX4(R0, R1, R2, R3, addr)                                              \
    asm volatile("ldmatrix.sync.aligned.m8n8.x4.shared.b16 {%0,%1,%2,%3}, [%4];" \
                 : "=r"(R0), "=r"(R1), "=r"(R2), "=r"(R3) : "r"(addr))

#define MMA16816(C, A0, A1, A2, A3, B0, B1)                                    \
    asm volatile("mma.sync.aligned.m16n8k16.row.col.f32.bf16.bf16.f32 "        \
                 "{%0,%1,%2,%3}, {%4,%5,%6,%7}, {%8,%9}, {%0,%1,%2,%3};"       \
                 : "+f"(C[0]), "+f"(C[1]), "+f"(C[2]), "+f"(C[3])              \
                 : "r"(A0), "r"(A1), "r"(A2), "r"(A3), "r"(B0), "r"(B1))

// ---------------- stage loader: A 128x32 hi+lo, B 128x32 hi+lo ----------------
__device__ __forceinline__ void issue_stage(uint32_t st,
                                            const __nv_bfloat16* __restrict__ Ahi,
                                            const __nv_bfloat16* __restrict__ Alo,
                                            const __nv_bfloat16* __restrict__ Bhi,
                                            const __nv_bfloat16* __restrict__ Blo,
                                            int ldA, int ldB, int kc, int tid) {
    const int col0 = kc * CHUNK_K;
#pragma unroll
    for (int i = 0; i < 4; i++) {
        int id = tid + 256 * i;
        int row = id >> 3, plane = (id >> 2) & 1, quad = id & 3;
        const __nv_bfloat16* src = (plane ? Alo : Ahi) + (size_t)row * ldA + col0 + quad * 8;
        CP_ASYNC16(st + row * 144 + plane * 64 + quad * 16, src);
    }
#pragma unroll
    for (int i = 0; i < 4; i++) {
        int id = tid + 256 * i;
        int row = id >> 3, plane = (id >> 2) & 1, quad = id & 3;
        const __nv_bfloat16* src = (plane ? Blo : Bhi) + (size_t)row * ldB + col0 + quad * 8;
        CP_ASYNC16(st + SMO_B + row * 144 + plane * 64 + quad * 16, src);
    }
    asm volatile("cp.async.commit_group;" ::: "memory");
}

// ---------------- engine: acc(128x128) += 3-term hi/lo GEMM over nChunks*32 K ----------------
// 256 threads, 8 warps 2(m) x 4(n), warp tile 64x32.
__device__ __forceinline__ void gemm3(const __nv_bfloat16* __restrict__ Ahi,
                                      const __nv_bfloat16* __restrict__ Alo,
                                      const __nv_bfloat16* __restrict__ Bhi,
                                      const __nv_bfloat16* __restrict__ Blo,
                                      int ldA, int ldB, int nChunks,
                                      uint32_t sb, float (&acc)[4][4][4]) {
    const int tid  = threadIdx.x;
    const int wid  = tid >> 5;
    const int lane = tid & 31;
    const int wm   = (wid & 1) * 64;
    const int wn   = (wid >> 1) * 32;
    const int lrow = lane & 15;
    const int lkB  = (lane >> 4) * 8;

    issue_stage(sb, Ahi, Alo, Bhi, Blo, ldA, ldB, 0, tid);
    issue_stage(sb + STAGE_BYTES, Ahi, Alo, Bhi, Blo, ldA, ldB, 1, tid);

    for (int kc = 0; kc < nChunks; kc++) {
        if (kc < nChunks - 1) asm volatile("cp.async.wait_group 1;" ::: "memory");
        else                  asm volatile("cp.async.wait_group 0;" ::: "memory");
        __syncthreads();

        if (kc + 2 < nChunks)
            issue_stage(sb + ((kc + 2) % 3) * STAGE_BYTES,
                        Ahi, Alo, Bhi, Blo, ldA, ldB, kc + 2, tid);

        const uint32_t sA = sb + (kc % 3) * STAGE_BYTES;
        const uint32_t sB = sA + SMO_B;

#pragma unroll
        for (int ks = 0; ks < 2; ks++) {
            uint32_t a[2][4][4];
#pragma unroll
            for (int mt = 0; mt < 4; mt++) {
                uint32_t ad = sA + ((wm + mt * 16 + lrow) * ASTR2 + ks * 16 + lkB) * 2;
                LDMX4(a[0][mt][0], a[0][mt][1], a[0][mt][2], a[0][mt][3], ad);
                LDMX4(a[1][mt][0], a[1][mt][1], a[1][mt][2], a[1][mt][3], ad + 64);
            }
            uint32_t b[2][2][4];
#pragma unroll
            for (int bg = 0; bg < 2; bg++) {
                uint32_t bd = sB + ((wn + bg * 16 + lrow) * ASTR2 + ks * 16 + lkB) * 2;
                LDMX4(b[0][bg][0], b[0][bg][1], b[0][bg][2], b[0][bg][3], bd);
                LDMX4(b[1][bg][0], b[1][bg][1], b[1][bg][2], b[1][bg][3], bd + 64);
            }
            // three product terms on the same fragments: hi.hi, hi.lo, lo.hi
#pragma unroll
            for (int t = 0; t < 3; t++) {
                const int pa = (t == 2) ? 1 : 0;
                const int pb = (t == 1) ? 1 : 0;
#pragma unroll
                for (int mt = 0; mt < 4; mt++)
#pragma unroll
                    for (int bg = 0; bg < 2; bg++) {
                        MMA16816(acc[mt][2 * bg],
                                 a[pa][mt][0], a[pa][mt][1], a[pa][mt][2], a[pa][mt][3],
                                 b[pb][bg][0], b[pb][bg][2]);
                        MMA16816(acc[mt][2 * bg + 1],
                                 a[pa][mt][0], a[pa][mt][1], a[pa][mt][2], a[pa][mt][3],
                                 b[pb][bg][1], b[pb][bg][3]);
                    }
            }
        }
    }
    __syncthreads();
}

// =================================================================================
// GEMM kernels
// =================================================================================
__global__ void __launch_bounds__(256) proj_tc(int mode) {
    extern __shared__ __align__(128) char smem[];
    float acc[4][4][4];
#pragma unroll
    for (int i = 0; i < 4; i++)
#pragma unroll
        for (int j = 0; j < 4; j++)
#pragma unroll
            for (int c = 0; c < 4; c++) acc[i][j][c] = 0.0f;

    const int m0 = blockIdx.y * 128;
    const int n0 = blockIdx.x * 128;
    gemm3(g_xhi + (size_t)m0 * HID, g_xlo + (size_t)m0 * HID,
          g_whi + (size_t)n0 * HID, g_wlo + (size_t)n0 * HID,
          HID, HID, HID / CHUNK_K, smem_u32(smem), acc);

    __nv_bfloat16 *dh, *dl;
    if (mode == 0)      { dh = g_qhi; dl = g_qlo; }
    else if (mode == 1) { dh = g_khi; dl = g_klo; }
    else                { dh = g_vhi; dl = g_vlo; }

    const int tid = threadIdx.x, wid = tid >> 5, lane = tid & 31;
    const int wm = (wid & 1) * 64, wn = (wid >> 1) * 32;
    const int g = lane >> 2, t2 = (lane & 3) * 2;
#pragma unroll
    for (int mt = 0; mt < 4; mt++)
#pragma unroll
        for (int ng = 0; ng < 4; ng++)
#pragma unroll
            for (int ci = 0; ci < 4; ci++) {
                int m = m0 + wm + mt * 16 + g + ((ci >> 1) << 3);
                int n = n0 + wn + ng * 8 + t2 + (ci & 1);
                float c = acc[mt][ng][ci];
                __nv_bfloat16 hi = __float2bfloat16(c);
                __nv_bfloat16 lo = __float2bfloat16(c - __bfloat162float(hi));
                dh[(size_t)m * HID + n] = hi;
                dl[(size_t)m * HID + n] = lo;
            }
}

__global__ void __launch_bounds__(256) scores_tc() {
    const int m0 = blockIdx.y * 128;
    const int n0 = blockIdx.x * 128;
    if (n0 > m0 + 127) return;                 // fully masked tile
    const int b = blockIdx.z;

    extern __shared__ __align__(128) char smem[];
    float acc[4][4][4];
#pragma unroll
    for (int i = 0; i < 4; i++)
#pragma unroll
        for (int j = 0; j < 4; j++)
#pragma unroll
            for (int c = 0; c < 4; c++) acc[i][j][c] = 0.0f;

    gemm3(g_qhi + (size_t)(b * SLEN + m0) * HID, g_qlo + (size_t)(b * SLEN + m0) * HID,
          g_khi + (size_t)(b * SLEN + n0) * HID, g_klo + (size_t)(b * SLEN + n0) * HID,
          HID, HID, HID / CHUNK_K, smem_u32(smem), acc);

    const int tid = threadIdx.x, wid = tid >> 5, lane = tid & 31;
    const int wm = (wid & 1) * 64, wn = (wid >> 1) * 32;
    const int g = lane >> 2, t2 = (lane & 3) * 2;
#pragma unroll
    for (int mt = 0; mt < 4; mt++)
#pragma unroll
        for (int ng = 0; ng < 4; ng++)
#pragma unroll
            for (int ci2 = 0; ci2 < 2; ci2++) {
                int m = m0 + wm + mt * 16 + g + ci2 * 8;
                int n = n0 + wn + ng * 8 + t2;
                float2 v = make_float2(acc[mt][ng][2 * ci2], acc[mt][ng][2 * ci2 + 1]);
                *(float2*)(g_S + ((size_t)b * SLEN + m) * SLEN + n) = v;
            }
}

__global__ void __launch_bounds__(256) pv_tc(float* __restrict__ out) {
    extern __shared__ __align__(128) char smem[];
    float acc[4][4][4];
#pragma unroll
    for (int i = 0; i < 4; i++)
#pragma unroll
        for (int j = 0; j < 4; j++)
#pragma unroll
            for (int c = 0; c < 4; c++) acc[i][j][c] = 0.0f;

    const int n0 = blockIdx.x * 128;
    const int m0 = (int)(gridDim.y - 1 - blockIdx.y) * 128;   // heavy tiles first
    const int b  = blockIdx.z;
    const int nc = (m0 + 128) / CHUNK_K;

    gemm3(g_phi + (size_t)(b * SLEN + m0) * SLEN, g_plo + (size_t)(b * SLEN + m0) * SLEN,
          g_vthi + (size_t)(b * HID + n0) * SLEN, g_vtlo + (size_t)(b * HID + n0) * SLEN,
          SLEN, SLEN, nc, smem_u32(smem), acc);

    const int tid = threadIdx.x, wid = tid >> 5, lane = tid & 31;
    const int wm = (wid & 1) * 64, wn = (wid >> 1) * 32;
    const int g = lane >> 2, t2 = (lane & 3) * 2;
#pragma unroll
    for (int mt = 0; mt < 4; mt++)
#pragma unroll
        for (int ng = 0; ng < 4; ng++)
#pragma unroll
            for (int ci2 = 0; ci2 < 2; ci2++) {
                int m = m0 + wm + mt * 16 + g + ci2 * 8;
                int n = n0 + wn + ng * 8 + t2;
                float2 v = make_float2(acc[mt][ng][2 * ci2], acc[mt][ng][2 * ci2 + 1]);
                *(float2*)(out + ((size_t)b * SLEN + m) * HID + n) = v;
            }
}

// ---------------- softmax: S -> phi/plo, zero-padded to 128-tile end ----------------
__global__ void __launch_bounds__(256) softmax_kernel() {
    __shared__ float buf[SLEN];
    __shared__ float red[16];
    const int row = blockIdx.x;
    const int i   = row & (SLEN - 1);
    const int tid = threadIdx.x, wid = tid >> 5, lane = tid & 31;
    const float scale = 0.03125f;   // 1/sqrt(1024)
    const float* srow = g_S + (size_t)row * SLEN;
    const int n    = i + 1;
    const int jpad = ((i >> 7) + 1) << 7;

    float lm = -3.0e38f;
    for (int j = tid; j < n; j += 256) lm = fmaxf(lm, srow[j]);
#pragma unroll
    for (int o = 16; o; o >>= 1) lm = fmaxf(lm, __shfl_xor_sync(0xffffffffu, lm, o));
    if (lane == 0) red[wid] = lm;
    __syncthreads();
    if (tid == 0) {
        float m = red[0];
#pragma unroll
        for (int w = 1; w < 8; w++) m = fmaxf(m, red[w]);
        red[0] = m;
    }
    __syncthreads();
    const float mx = red[0];

    float ls = 0.0f;
    for (int j = tid; j < n; j += 256) {
        float e = __expf((srow[j] - mx) * scale);
        buf[j] = e;
        ls += e;
    }
#pragma unroll
    for (int o = 16; o; o >>= 1) ls += __shfl_xor_sync(0xffffffffu, ls, o);
    if (lane == 0) red[8 + wid] = ls;
    __syncthreads();
    if (tid == 0) {
        float s = 0.0f;
#pragma unroll
        for (int w = 0; w < 8; w++) s += red[8 + w];
        red[8] = 1.0f / s;
    }
    __syncthreads();
    const float inv = red[8];

    __nv_bfloat16* ph = g_phi + (size_t)row * SLEN;
    __nv_bfloat16* pl = g_plo + (size_t)row * SLEN;
    for (int j = tid; j < jpad; j += 256) {
        float p = (j < n) ? buf[j] * inv : 0.0f;
        __nv_bfloat16 hi = __float2bfloat16(p);
        __nv_bfloat16 lo = __float2bfloat16(p - __bfloat162float(hi));
        ph[j] = hi;
        pl[j] = lo;
    }
}

// ---------------- splits + V transpose ----------------
__global__ void __launch_bounds__(256) split_x(const float* __restrict__ x) {
    size_t idx = (size_t)blockIdx.x * 256 + threadIdx.x;
    float v = x[idx];
    __nv_bfloat16 hi = __float2bfloat16(v);
    __nv_bfloat16 lo = __float2bfloat16(v - __bfloat162float(hi));
    g_xhi[idx] = hi;
    g_xlo[idx] = lo;
}

__global__ void __launch_bounds__(256) split_w(const float* __restrict__ W) {
    size_t idx = (size_t)blockIdx.x * 256 + threadIdx.x;
    float v = W[idx];
    __nv_bfloat16 hi = __float2bfloat16(v);
    __nv_bfloat16 lo = __float2bfloat16(v - __bfloat162float(hi));
    g_whi[idx] = hi;
    g_wlo[idx] = lo;
}

__global__ void __launch_bounds__(256) transpose_v() {
    __shared__ __nv_bfloat16 th[32][33];
    __shared__ __nv_bfloat16 tl[32][33];
    const int b  = blockIdx.z;
    const int h0 = blockIdx.x * 32;
    const int s0 = blockIdx.y * 32;
    const int tx = threadIdx.x, ty = threadIdx.y;   // 32 x 8
    for (int r = ty; r < 32; r += 8) {
        size_t src = ((size_t)b * SLEN + s0 + r) * HID + h0 + tx;
        th[r][tx] = g_vhi[src];
        tl[r][tx] = g_vlo[src];
    }
    __syncthreads();
    for (int r = ty; r < 32; r += 8) {
        size_t dst = ((size_t)b * HID + h0 + r) * SLEN + s0 + tx;
        g_vthi[dst] = th[tx][r];
        g_vtlo[dst] = tl[tx][r];
    }
}

// =================================================================================
// Launch
// =================================================================================
extern "C" void kernel_launch(void* const* d_in, const int* in_sizes, int n_in,
                              void* d_out, int out_size) {
    (void)in_sizes; (void)n_in; (void)out_size;
    const float* x  = (const float*)d_in[0];
    const float* Wq = (const float*)d_in[1];
    const float* Wk = (const float*)d_in[2];
    const float* Wv = (const float*)d_in[3];
    float* out = (float*)d_out;

    static bool attr_set = false;
    if (!attr_set) {
        cudaFuncSetAttribute(proj_tc,   cudaFuncAttributeMaxDynamicSharedMemorySize, ENG_SMEM);
        cudaFuncSetAttribute(scores_tc, cudaFuncAttributeMaxDynamicSharedMemorySize, ENG_SMEM);
        cudaFuncSetAttribute(pv_tc,     cudaFuncAttributeMaxDynamicSharedMemorySize, ENG_SMEM);
        attr_set = true;
    }

    split_x<<<(MTOT * HID) / 256, 256>>>(x);

    dim3 pgrid(HID / 128, MTOT / 128);                 // (8, 128)
    split_w<<<(HID * HID) / 256, 256>>>(Wq);
    proj_tc<<<pgrid, 256, ENG_SMEM>>>(0);
    split_w<<<(HID * HID) / 256, 256>>>(Wk);
    proj_tc<<<pgrid, 256, ENG_SMEM>>>(1);
    split_w<<<(HID * HID) / 256, 256>>>(Wv);
    proj_tc<<<pgrid, 256, ENG_SMEM>>>(2);

    transpose_v<<<dim3(HID / 32, SLEN / 32, BATCH), dim3(32, 8)>>>();

    scores_tc<<<dim3(SLEN / 128, SLEN / 128, BATCH), 256, ENG_SMEM>>>();
    softmax_kernel<<<MTOT, 256>>>();
    pv_tc<<<dim3(HID / 128, SLEN / 128, BATCH), 256, ENG_SMEM>>>(out);
}